// round 15
// baseline (speedup 1.0000x reference)
#include <cuda_runtime.h>
#include <cuda_bf16.h>

// roi_feature: dual bilinear grid_sample with a shared 16x16 grid per batch.
// inputs: [0] original_features f32 (32,256,64,64)
//         [1] lab f32 (32,1,5)
//         [2] attack_features f32 (32,256,64,64)
// output: concat(out1, out2), each (32,256,16,16) f32.
//
// R15 strategy: float2 corner-merge, near-zero overfetch. Per sampled row,
// one aligned LDG.64 at (xc0 & ~1) covers xc0 always and xc1 when xc0 is
// even; a predicated LDG.32 (~50% lanes) covers the odd case. Same LDG
// instruction count as the 12.77us baseline but ~half the L1tex wavefronts
// (sibling-corner line replays eliminated). Decisive test: wavefront-bound
// -> ~10.5-11.5us; LSU-issue-bound -> unchanged.

#define B_   32
#define C_   256
#define H_   64
#define W_   64
#define BIN_ 16
#define CH_PER_BLK 4

__global__ __launch_bounds__(256, 3)
void roi_feature_kernel(const float* __restrict__ orig,
                        const float* __restrict__ lab,
                        const float* __restrict__ att,
                        float* __restrict__ out)
{
    const int b      = blockIdx.x;           // 0..31
    const int cchunk = blockIdx.y;           // 0..63, 4 channels each
    const int t      = threadIdx.x;          // 0..255
    const int i      = t >> 4;               // bin row  (drives y)
    const int j      = t & 15;               // bin col  (drives x)

    const float* L = lab + b * 5;
    const float l1 = __ldg(L + 1);
    const float l2 = __ldg(L + 2);
    const float l3 = __ldg(L + 3);
    const float l4 = __ldg(L + 4);

    // grid[...,0] -> x pixel (from j); grid[...,1] -> y pixel (from i)
    const float gx = 2.0f * (float)(j - BIN_ / 2) * l3 / (float)BIN_ + (l1 * 2.0f - 1.0f);
    const float gy = 2.0f * (float)(i - BIN_ / 2) * l4 / (float)BIN_ + (l2 * 2.0f - 1.0f);

    const float x = ((gx + 1.0f) * (float)W_ - 1.0f) * 0.5f;
    const float y = ((gy + 1.0f) * (float)H_ - 1.0f) * 0.5f;

    const float x0f = floorf(x);
    const float y0f = floorf(y);
    const int x0 = (int)x0f;
    const int y0 = (int)y0f;
    const int x1 = x0 + 1;
    const int y1 = y0 + 1;

    const float wx1 = x - x0f, wx0 = 1.0f - wx1;
    const float wy1 = y - y0f, wy0 = 1.0f - wy1;

    const float vx0 = (x0 >= 0 && x0 < W_) ? 1.0f : 0.0f;
    const float vx1 = (x1 >= 0 && x1 < W_) ? 1.0f : 0.0f;
    const float vy0 = (y0 >= 0 && y0 < H_) ? 1.0f : 0.0f;
    const float vy1 = (y1 >= 0 && y1 < H_) ? 1.0f : 0.0f;

    const float w00 = wx0 * wy0 * vx0 * vy0;
    const float w01 = wx1 * wy0 * vx1 * vy0;
    const float w10 = wx0 * wy1 * vx0 * vy1;
    const float w11 = wx1 * wy1 * vx1 * vy1;

    const int xc0 = min(max(x0, 0), W_ - 1);
    const int xc1 = min(max(x1, 0), W_ - 1);
    const int yc0 = min(max(y0, 0), H_ - 1);
    const int yc1 = min(max(y1, 0), H_ - 1);

    // aligned float2 window: a covers xc0 (elem s); xc1 unless e1 == 2
    const int a  = xc0 & ~1;
    const int s  = xc0 & 1;          // elem of xc0 in window
    const int e1 = xc1 - a;          // 0, 1, or 2
    const bool needE = (e1 == 2);    // xc1 = a+2 <= 63, in-bounds by construction

    const int rV0 = yc0 * W_ + a;
    const int rV1 = yc1 * W_ + a;
    const int rE0 = yc0 * W_ + xc1;
    const int rE1 = yc1 * W_ + xc1;

    const size_t plane   = (size_t)H_ * W_;                     // 4096
    const size_t base    = ((size_t)b * C_ + (size_t)cchunk * CH_PER_BLK) * plane;
    const size_t outbase = ((size_t)b * C_ + (size_t)cchunk * CH_PER_BLK) * (BIN_ * BIN_) + t;
    const size_t out2off = (size_t)B_ * C_ * BIN_ * BIN_;       // 2,097,152

    // ---- Phase 1: front-batch all loads ----
    float2 PV0[CH_PER_BLK], PV1[CH_PER_BLK];
    float2 QV0[CH_PER_BLK], QV1[CH_PER_BLK];
    float  PE0[CH_PER_BLK], PE1[CH_PER_BLK];
    float  QE0[CH_PER_BLK], QE1[CH_PER_BLK];

    #pragma unroll
    for (int cc = 0; cc < CH_PER_BLK; ++cc) {
        const float* pp = orig + base + (size_t)cc * plane;
        PV0[cc] = __ldg((const float2*)(pp + rV0));
        PV1[cc] = __ldg((const float2*)(pp + rV1));
    }
    #pragma unroll
    for (int cc = 0; cc < CH_PER_BLK; ++cc) {
        const float* qq = att + base + (size_t)cc * plane;
        QV0[cc] = __ldg((const float2*)(qq + rV0));
        QV1[cc] = __ldg((const float2*)(qq + rV1));
    }
    #pragma unroll
    for (int cc = 0; cc < CH_PER_BLK; ++cc) {
        const float* pp = orig + base + (size_t)cc * plane;
        const float* qq = att  + base + (size_t)cc * plane;
        PE0[cc] = needE ? __ldg(pp + rE0) : 0.0f;
        PE1[cc] = needE ? __ldg(pp + rE1) : 0.0f;
        QE0[cc] = needE ? __ldg(qq + rE0) : 0.0f;
        QE1[cc] = needE ? __ldg(qq + rE1) : 0.0f;
    }

    // ---- Phase 2: select corners, compute, store ----
    #pragma unroll
    for (int cc = 0; cc < CH_PER_BLK; ++cc) {
        const float p00 = s ? PV0[cc].y : PV0[cc].x;
        const float p10 = s ? PV1[cc].y : PV1[cc].x;
        const float p01 = needE ? PE0[cc] : (e1 ? PV0[cc].y : PV0[cc].x);
        const float p11 = needE ? PE1[cc] : (e1 ? PV1[cc].y : PV1[cc].x);

        const float q00 = s ? QV0[cc].y : QV0[cc].x;
        const float q10 = s ? QV1[cc].y : QV1[cc].x;
        const float q01 = needE ? QE0[cc] : (e1 ? QV0[cc].y : QV0[cc].x);
        const float q11 = needE ? QE1[cc] : (e1 ? QV1[cc].y : QV1[cc].x);

        const float r1 = p00 * w00 + p01 * w01 + p10 * w10 + p11 * w11;
        const float r2 = q00 * w00 + q01 * w01 + q10 * w10 + q11 * w11;
        out[outbase + (size_t)cc * (BIN_ * BIN_)]           = r1;
        out[out2off + outbase + (size_t)cc * (BIN_ * BIN_)] = r2;
    }
}

extern "C" void kernel_launch(void* const* d_in, const int* in_sizes, int n_in,
                              void* d_out, int out_size)
{
    const float* orig = (const float*)d_in[0];
    const float* lab  = (const float*)d_in[1];
    const float* att  = (const float*)d_in[2];
    float* out        = (float*)d_out;

    dim3 grid(B_, C_ / CH_PER_BLK);   // (32, 64)
    roi_feature_kernel<<<grid, 256>>>(orig, lab, att, out);
}

// round 17
// speedup vs baseline: 1.1579x; 1.1579x over previous
#include <cuda_runtime.h>
#include <cuda_bf16.h>

// roi_feature: dual bilinear grid_sample with a shared 16x16 grid per batch.
// inputs: [0] original_features f32 (32,256,64,64)
//         [1] lab f32 (32,1,5)
//         [2] attack_features f32 (32,256,64,64)
// output: concat(out1, out2), each (32,256,16,16) f32.
//
// Final (R16): proven-best R2 structure (12.768us — measured floor across
// nine structural variants: MLP, occupancy, waves, ordering, SMEM staging,
// vector windows, cache policy, lane remap, corner merges) with all index
// arithmetic in 32-bit (every offset < 2^25 elements), halving the IMAD
// address chain. Front-batched 32-load gather, CH_PER_BLK=4,
// launch_bounds(256,4).

#define B_   32
#define C_   256
#define H_   64
#define W_   64
#define BIN_ 16
#define CH_PER_BLK 4

__global__ __launch_bounds__(256, 4)
void roi_feature_kernel(const float* __restrict__ orig,
                        const float* __restrict__ lab,
                        const float* __restrict__ att,
                        float* __restrict__ out)
{
    const int b      = blockIdx.x;           // 0..31
    const int cchunk = blockIdx.y;           // 0..63, 4 channels each
    const int t      = threadIdx.x;          // 0..255
    const int i      = t >> 4;               // bin row  (drives y)
    const int j      = t & 15;               // bin col  (drives x)

    const float* L = lab + b * 5;
    const float l1 = __ldg(L + 1);
    const float l2 = __ldg(L + 2);
    const float l3 = __ldg(L + 3);
    const float l4 = __ldg(L + 4);

    // grid[...,0] -> x pixel (from j); grid[...,1] -> y pixel (from i)
    const float gx = 2.0f * (float)(j - BIN_ / 2) * l3 / (float)BIN_ + (l1 * 2.0f - 1.0f);
    const float gy = 2.0f * (float)(i - BIN_ / 2) * l4 / (float)BIN_ + (l2 * 2.0f - 1.0f);

    const float x = ((gx + 1.0f) * (float)W_ - 1.0f) * 0.5f;
    const float y = ((gy + 1.0f) * (float)H_ - 1.0f) * 0.5f;

    const float x0f = floorf(x);
    const float y0f = floorf(y);
    const int x0 = (int)x0f;
    const int y0 = (int)y0f;
    const int x1 = x0 + 1;
    const int y1 = y0 + 1;

    const float wx1 = x - x0f, wx0 = 1.0f - wx1;
    const float wy1 = y - y0f, wy0 = 1.0f - wy1;

    const float vx0 = (x0 >= 0 && x0 < W_) ? 1.0f : 0.0f;
    const float vx1 = (x1 >= 0 && x1 < W_) ? 1.0f : 0.0f;
    const float vy0 = (y0 >= 0 && y0 < H_) ? 1.0f : 0.0f;
    const float vy1 = (y1 >= 0 && y1 < H_) ? 1.0f : 0.0f;

    const float w00 = wx0 * wy0 * vx0 * vy0;
    const float w01 = wx1 * wy0 * vx1 * vy0;
    const float w10 = wx0 * wy1 * vx0 * vy1;
    const float w11 = wx1 * wy1 * vx1 * vy1;

    const int xc0 = min(max(x0, 0), W_ - 1);
    const int xc1 = min(max(x1, 0), W_ - 1);
    const int yc0 = min(max(y0, 0), H_ - 1);
    const int yc1 = min(max(y1, 0), H_ - 1);

    const unsigned o00 = (unsigned)(yc0 * W_ + xc0);
    const unsigned o01 = (unsigned)(yc0 * W_ + xc1);
    const unsigned o10 = (unsigned)(yc1 * W_ + xc0);
    const unsigned o11 = (unsigned)(yc1 * W_ + xc1);

    // all 32-bit: max base = 32*256*4096 = 33,554,432 < 2^31
    const unsigned plane   = (unsigned)(H_ * W_);                         // 4096
    const unsigned base    = ((unsigned)b * C_ + (unsigned)cchunk * CH_PER_BLK) * plane;
    const unsigned outbase = ((unsigned)b * C_ + (unsigned)cchunk * CH_PER_BLK) * (BIN_ * BIN_) + (unsigned)t;
    const unsigned out2off = (unsigned)(B_ * C_ * BIN_ * BIN_);           // 2,097,152

    // ---- Phase 1: issue ALL gather loads (32 in flight per thread) ----
    float p[CH_PER_BLK][4];
    float q[CH_PER_BLK][4];

    #pragma unroll
    for (int cc = 0; cc < CH_PER_BLK; ++cc) {
        const float* pp = orig + base + (unsigned)cc * plane;
        p[cc][0] = __ldg(pp + o00);
        p[cc][1] = __ldg(pp + o01);
        p[cc][2] = __ldg(pp + o10);
        p[cc][3] = __ldg(pp + o11);
    }
    #pragma unroll
    for (int cc = 0; cc < CH_PER_BLK; ++cc) {
        const float* qq = att + base + (unsigned)cc * plane;
        q[cc][0] = __ldg(qq + o00);
        q[cc][1] = __ldg(qq + o01);
        q[cc][2] = __ldg(qq + o10);
        q[cc][3] = __ldg(qq + o11);
    }

    // ---- Phase 2: compute + store ----
    #pragma unroll
    for (int cc = 0; cc < CH_PER_BLK; ++cc) {
        const float r1 = p[cc][0] * w00 + p[cc][1] * w01 + p[cc][2] * w10 + p[cc][3] * w11;
        const float r2 = q[cc][0] * w00 + q[cc][1] * w01 + q[cc][2] * w10 + q[cc][3] * w11;
        out[outbase + (unsigned)cc * (BIN_ * BIN_)]           = r1;
        out[out2off + outbase + (unsigned)cc * (BIN_ * BIN_)] = r2;
    }
}

extern "C" void kernel_launch(void* const* d_in, const int* in_sizes, int n_in,
                              void* d_out, int out_size)
{
    const float* orig = (const float*)d_in[0];
    const float* lab  = (const float*)d_in[1];
    const float* att  = (const float*)d_in[2];
    float* out        = (float*)d_out;

    dim3 grid(B_, C_ / CH_PER_BLK);   // (32, 64)
    roi_feature_kernel<<<grid, 256>>>(orig, lab, att, out);
}